// round 9
// baseline (speedup 1.0000x reference)
#include <cuda_runtime.h>

// Problem shapes (fixed per reference setup_inputs)
#define BB  2
#define SS  2048
#define HH  4096
#define NHD 32
#define NSL 100
#define NP  128          // slots padded to 128
#define DD  64
#define BSR (BB*SS)      // 4096 rows

typedef unsigned long long ull;

// -------- scratch (no allocations allowed) --------
__device__ float g_gate[BSR];
__device__ float g_KW[HH*NP];       // (W_q^T keys^T)[h][n], pad n>=100 with 0
__device__ float g_logrelp[NP];     // log(rel+eps), pad = -1e30
__device__ float g_attn[BSR*NP];    // softmax(scores), un-gated
__device__ unsigned g_row_ticket;

// -------- packed f32x2 helpers --------
__device__ __forceinline__ ull pk2(float lo, float hi){
    ull r; asm("mov.b64 %0, {%1, %2};" : "=l"(r) : "f"(lo), "f"(hi)); return r;
}
__device__ __forceinline__ void upk2(ull v, float& lo, float& hi){
    asm("mov.b64 {%0, %1}, %2;" : "=f"(lo), "=f"(hi) : "l"(v));
}
__device__ __forceinline__ void fma2(ull& d, ull a, ull b){
    asm("fma.rn.f32x2 %0, %1, %2, %0;" : "+l"(d) : "l"(a), "l"(b));
}
union F4U { float4 f; ull u[2]; };

// ============================================================
// prep_kw: KW[h][n] = sum_d Wq[d][h]*keys[n][d]
// grid (16, 8): block y owns n in [16y, 16y+16) -> 128 CTAs
// ============================================================
__global__ __launch_bounds__(256)
void prep_kw(const float* __restrict__ Wq,
             const float* __restrict__ keys,
             const float* __restrict__ rel)
{
    __shared__ float sk[16*DD];
    int t = threadIdx.x;
    int n0 = blockIdx.y * 16;
    for (int i = t; i < 16*DD; i += 256) {
        int n = i >> 6, d = i & 63;
        sk[i] = ((n0 + n) < NSL) ? keys[(n0+n)*DD + d] : 0.f;
    }
    __syncthreads();

    int h = blockIdx.x*256 + t;
    float wv[DD];
    #pragma unroll
    for (int d = 0; d < DD; ++d) wv[d] = Wq[(size_t)d*HH + h];

    #pragma unroll 4
    for (int n = 0; n < 16; ++n) {
        float acc = 0.f;
        const float* kn = sk + n*DD;
        #pragma unroll
        for (int d = 0; d < DD; ++d) acc += wv[d]*kn[d];
        g_KW[(size_t)h*NP + n0 + n] = acc;
    }
    if (blockIdx.x == 0 && blockIdx.y == 0 && t < NP)
        g_logrelp[t] = (t < NSL) ? __logf(rel[t] + 1e-10f) : -1e30f;
    if (blockIdx.x == 0 && blockIdx.y == 0 && t == 0) g_row_ticket = 0u;
}

// ============================================================
// mega: grid = 296 (2 CTAs/SM).
//   blocks [0,148)    : entropy ticket loop from t=0
//   blocks [148,276)  : scores tile -> softmax -> HALF aux GEMM
//                       (cols [0,2048), un-gated, 1 col/thread,
//                       aA[16] only -> no spills), then entropy
//   blocks [276,296)  : entropy
// ============================================================
#define NENT  148
#define NSCORE 128
#define NGRID (NENT + NSCORE + 20)   // 296

#define SKC 64
#define NCH (HH/SKC)     // 64 chunks
#define SCORES_SMEM (32*SKC*2 + SKC*NP)   // floats: 12288 -> 49152B

__device__ __forceinline__ void entropy_loop(const float* __restrict__ paw,
                                             float w1, float bb,
                                             unsigned* s_work, float* red)
{
    int t = threadIdx.x;
    for (;;) {
        __syncthreads();
        if (t == 0) *s_work = atomicAdd(&g_row_ticket, 1u);
        __syncthreads();
        unsigned row = *s_work;
        if (row >= BSR) break;

        size_t b = (size_t)(row >> 11);
        size_t s = (size_t)(row & 2047);
        const float* base = paw + ((b*NHD)*SS + s) * (size_t)SS;

        float4 a0 = make_float4(0.f,0.f,0.f,0.f);
        float4 a1 = make_float4(0.f,0.f,0.f,0.f);
        for (int h0 = 0; h0 < NHD; h0 += 8) {
            float4 x0[8], x1[8];
            #pragma unroll
            for (int u = 0; u < 8; ++u) {
                const float4* p = (const float4*)(base + (size_t)(h0+u)*SS*SS);
                x0[u] = p[t];
                x1[u] = p[t + 256];
            }
            #pragma unroll
            for (int u = 0; u < 8; ++u) {
                a0.x += x0[u].x; a0.y += x0[u].y; a0.z += x0[u].z; a0.w += x0[u].w;
                a1.x += x1[u].x; a1.y += x1[u].y; a1.z += x1[u].z; a1.w += x1[u].w;
            }
        }
        const float inv = 1.0f / 32.0f;
        float v[8] = {a0.x,a0.y,a0.z,a0.w,a1.x,a1.y,a1.z,a1.w};
        float loc = 0.f;
        #pragma unroll
        for (int i = 0; i < 8; ++i) {
            float a = v[i] * inv;
            loc += a * __logf(a + 1e-10f);
        }
        #pragma unroll
        for (int o = 16; o; o >>= 1) loc += __shfl_xor_sync(0xffffffffu, loc, o);
        if ((t & 31) == 0) red[t >> 5] = loc;
        __syncthreads();
        if (t == 0) {
            float tot = 0.f;
            #pragma unroll
            for (int i = 0; i < 8; ++i) tot += red[i];
            float e = -tot;
            float g = 1.0f / (1.0f + __expf(-(w1*e + bb)));
            if (e < 0.5f)       g = 0.f;
            else if (e > 2.0f)  g = fminf(g, 0.8f);
            g_gate[row] = g;
        }
    }
}

__global__ __launch_bounds__(256, 2)
void mega_kernel(const float* __restrict__ hidden,
                 const float* __restrict__ paw,
                 const float* __restrict__ vals,
                 const float* __restrict__ w1p,
                 const float* __restrict__ bp,
                 float* __restrict__ out)
{
    extern __shared__ float smraw[];
    __shared__ float red[8];
    __shared__ unsigned s_work;
    int t = threadIdx.x;
    int bid = blockIdx.x;

    if (bid >= NENT && bid < NENT + NSCORE) {
        // =================== scores tile ===================
        float2* sh = (float2*)smraw;             // [32][SKC] dup pairs, 16KB
        float*  sw = smraw + 32*SKC*2;           // [SKC][NP], 32KB
        int w = t>>5, lane = t&31;
        int row0 = (bid - NENT)*32;

        float4 ph[2], pw[8];
        #pragma unroll
        for (int i = 0; i < 2; ++i) {
            int idx = t + i*256, rr = idx>>4, c4 = idx&15;
            ph[i] = *(const float4*)(hidden + (size_t)(row0+rr)*HH + (c4<<2));
        }
        #pragma unroll
        for (int i = 0; i < 8; ++i) {
            int idx = t + i*256, kk = idx>>5, c4 = idx&31;
            pw[i] = *(const float4*)(g_KW + (size_t)kk*NP + (c4<<2));
        }

        ull a[4][2] = {{0,0},{0,0},{0,0},{0,0}};

        for (int c = 0; c < NCH; ++c) {
            __syncthreads();
            #pragma unroll
            for (int i = 0; i < 2; ++i) {
                int idx = t + i*256, rr = idx>>4, c4 = idx&15;
                float2* d = &sh[rr*SKC + (c4<<2)];
                d[0] = make_float2(ph[i].x, ph[i].x);
                d[1] = make_float2(ph[i].y, ph[i].y);
                d[2] = make_float2(ph[i].z, ph[i].z);
                d[3] = make_float2(ph[i].w, ph[i].w);
            }
            #pragma unroll
            for (int i = 0; i < 8; ++i) {
                int idx = t + i*256, kk = idx>>5, c4 = idx&31;
                *(float4*)(sw + kk*NP + (c4<<2)) = pw[i];
            }
            __syncthreads();

            if (c + 1 < NCH) {
                int k0 = (c+1)*SKC;
                #pragma unroll
                for (int i = 0; i < 2; ++i) {
                    int idx = t + i*256, rr = idx>>4, c4 = idx&15;
                    ph[i] = *(const float4*)(hidden + (size_t)(row0+rr)*HH + k0 + (c4<<2));
                }
                #pragma unroll
                for (int i = 0; i < 8; ++i) {
                    int idx = t + i*256, kk = idx>>5, c4 = idx&31;
                    pw[i] = *(const float4*)(g_KW + (size_t)(k0+kk)*NP + (c4<<2));
                }
            }

            const ull* h0 = (const ull*)&sh[(w*4+0)*SKC];
            const ull* h1 = (const ull*)&sh[(w*4+1)*SKC];
            const ull* h2 = (const ull*)&sh[(w*4+2)*SKC];
            const ull* h3 = (const ull*)&sh[(w*4+3)*SKC];
            #pragma unroll 8
            for (int k = 0; k < SKC; ++k) {
                F4U kw; kw.f = *(const float4*)(sw + k*NP + (lane<<2));
                ull hh0 = h0[k], hh1 = h1[k], hh2 = h2[k], hh3 = h3[k];
                fma2(a[0][0], kw.u[0], hh0); fma2(a[0][1], kw.u[1], hh0);
                fma2(a[1][0], kw.u[0], hh1); fma2(a[1][1], kw.u[1], hh1);
                fma2(a[2][0], kw.u[0], hh2); fma2(a[2][1], kw.u[1], hh2);
                fma2(a[3][0], kw.u[0], hh3); fma2(a[3][1], kw.u[1], hh3);
            }
        }

        // ---------- softmax per row; write g_attn; keep for pack ----------
        float4 lr = *(const float4*)(g_logrelp + (lane<<2));
        float at[4][4];
        #pragma unroll
        for (int j = 0; j < 4; ++j) {
            int row = row0 + w*4 + j;
            float s0,s1,s2,s3;
            upk2(a[j][0], s0, s1); upk2(a[j][1], s2, s3);
            s0 = 0.125f*s0 + lr.x; s1 = 0.125f*s1 + lr.y;
            s2 = 0.125f*s2 + lr.z; s3 = 0.125f*s3 + lr.w;
            float m = fmaxf(fmaxf(s0,s1), fmaxf(s2,s3));
            #pragma unroll
            for (int o = 16; o; o >>= 1) m = fmaxf(m, __shfl_xor_sync(0xffffffffu, m, o));
            float e0 = __expf(s0-m), e1 = __expf(s1-m);
            float e2 = __expf(s2-m), e3 = __expf(s3-m);
            float sum = e0+e1+e2+e3;
            #pragma unroll
            for (int o = 16; o; o >>= 1) sum += __shfl_xor_sync(0xffffffffu, sum, o);
            float invs = 1.0f / sum;
            at[j][0] = e0*invs; at[j][1] = e1*invs;
            at[j][2] = e2*invs; at[j][3] = e3*invs;
            *(float4*)(g_attn + (size_t)row*NP + (lane<<2)) =
                make_float4(at[j][0], at[j][1], at[j][2], at[j][3]);
        }

        // ---------- pack attn2[n][row-pair] into smem ----------
        __syncthreads();                 // mainloop smem reads done
        ull* attn2 = (ull*)smraw;        // NSL*16 ull = 12.8KB
        #pragma unroll
        for (int k = 0; k < 4; ++k) {
            int n = (lane<<2) + k;
            if (n < NSL) {
                attn2[n*16 + 2*w]     = pk2(at[0][k], at[1][k]);
                attn2[n*16 + 2*w + 1] = pk2(at[2][k], at[3][k]);
            }
        }
        __syncthreads();

        // ---- HALF aux GEMM: cols [0,2048), 1 col/thread, un-gated ----
        #pragma unroll 1
        for (int pass = 0; pass < 8; ++pass) {
            int c = pass*256 + t;
            ull aA[16];
            #pragma unroll
            for (int rp = 0; rp < 16; ++rp) aA[rp] = 0;

            float vr[4];
            #pragma unroll
            for (int i = 0; i < 4; ++i) vr[i] = vals[(size_t)i*HH + c];

            #pragma unroll 1
            for (int n = 0; n < NSL; ++n) {
                int np = (n + 4 < NSL) ? n + 4 : NSL-1;
                float nv = vals[(size_t)np*HH + c];
                int sl = n & 3;
                ull vv = pk2(vr[sl], vr[sl]);
                const float4* arow = (const float4*)(attn2 + n*16);
                #pragma unroll
                for (int j = 0; j < 8; ++j) {
                    F4U u; u.f = arow[j];
                    fma2(aA[2*j],   u.u[0], vv);
                    fma2(aA[2*j+1], u.u[1], vv);
                }
                vr[sl] = nv;
            }
            #pragma unroll
            for (int rp = 0; rp < 16; ++rp) {
                float x, y;
                size_t rb = (size_t)(row0 + rp*2) * HH;
                upk2(aA[rp], x, y);
                out[rb + c] = x;
                out[rb + HH + c] = y;
            }
        }
    }

    // =================== entropy (all CTAs) ===================
    entropy_loop(paw, w1p[0], bp[0], &s_work, red);
}

// ============================================================
// output2: grid (128 row-tiles, 8) x 512 thr
//   y in [0,4): stream-gate cols [0,2048): out = primary + g*out
//   y in [4,8): gated aux GEMM for cols [2048,4096)
// ============================================================
__global__ __launch_bounds__(512, 2)
void output2_kernel(const float* __restrict__ primary,
                    const float* __restrict__ vals,
                    float* __restrict__ out)
{
    __shared__ ull attn2[NSL*16];   // [n][row-pair]
    __shared__ float sg[32];
    int t = threadIdx.x;
    int row0 = blockIdx.x*32;

    if (t < 32) sg[t] = g_gate[row0 + t];
    __syncthreads();

    if (blockIdx.y < 4) {
        // ---- stream path: cols [0,2048) hold un-gated aux ----
        int c = blockIdx.y*512 + t;
        #pragma unroll 4
        for (int r = 0; r < 32; ++r) {
            size_t idx = (size_t)(row0 + r)*HH + c;
            out[idx] = primary[idx] + sg[r]*out[idx];
        }
        return;
    }

    // ---- GEMM path: cols [2048,4096) ----
    int c = 2048 + (blockIdx.y - 4)*512 + t;

    for (int idx = t; idx < NSL*16; idx += 512) {
        int n = idx >> 4, rp = idx & 15;
        float a0 = g_attn[(size_t)(row0 + 2*rp  )*NP + n];
        float a1 = g_attn[(size_t)(row0 + 2*rp+1)*NP + n];
        attn2[n*16 + rp] = pk2(a0*sg[2*rp], a1*sg[2*rp+1]);
    }
    __syncthreads();

    ull acc[16];
    #pragma unroll
    for (int rp = 0; rp < 16; ++rp) {
        size_t rb = (size_t)(row0 + rp*2) * HH;
        acc[rp] = pk2(primary[rb + c], primary[rb + HH + c]);
    }

    float vr[4];
    #pragma unroll
    for (int i = 0; i < 4; ++i) vr[i] = vals[(size_t)i*HH + c];

    for (int n = 0; n < NSL; ++n) {
        int np = (n + 4 < NSL) ? n + 4 : NSL-1;
        float nv = vals[(size_t)np*HH + c];
        int sl = n & 3;
        ull vv = pk2(vr[sl], vr[sl]);
        const float4* arow = (const float4*)(attn2 + n*16);
        #pragma unroll
        for (int j = 0; j < 8; ++j) {
            F4U u; u.f = arow[j];        // broadcast LDS.128
            fma2(acc[2*j],   u.u[0], vv);
            fma2(acc[2*j+1], u.u[1], vv);
        }
        vr[sl] = nv;
    }

    #pragma unroll
    for (int rp = 0; rp < 16; ++rp) {
        float x, y;
        size_t rb = (size_t)(row0 + rp*2) * HH;
        upk2(acc[rp], x, y);
        out[rb + c] = x;
        out[rb + HH + c] = y;
    }
}

// ============================================================
extern "C" void kernel_launch(void* const* d_in, const int* in_sizes, int n_in,
                              void* d_out, int out_size)
{
    const float* hidden  = (const float*)d_in[0];  // [B,S,H]
    const float* primary = (const float*)d_in[1];  // [B,S,H]
    const float* paw     = (const float*)d_in[2];  // [B,NH,S,S]
    const float* rel     = (const float*)d_in[3];  // [NS]
    const float* Wq      = (const float*)d_in[4];  // [D,H]
    const float* keys    = (const float*)d_in[5];  // [NS,D]
    const float* vals    = (const float*)d_in[6];  // [NS,H]
    const float* gw1     = (const float*)d_in[7];  // scalar
    const float* gb      = (const float*)d_in[8];  // scalar
    float* out = (float*)d_out;

    cudaFuncSetAttribute(mega_kernel,
                         cudaFuncAttributeMaxDynamicSharedMemorySize,
                         SCORES_SMEM * (int)sizeof(float));

    prep_kw<<<dim3(HH/256, 8), 256>>>(Wq, keys, rel);
    mega_kernel<<<NGRID, 256, SCORES_SMEM * sizeof(float)>>>(
        hidden, paw, vals, gw1, gb, out);
    output2_kernel<<<dim3(BSR/32, 8), 512>>>(primary, vals, out);
}

// round 10
// speedup vs baseline: 1.7046x; 1.7046x over previous
#include <cuda_runtime.h>

// Problem shapes (fixed per reference setup_inputs)
#define BB  2
#define SS  2048
#define HH  4096
#define NHD 32
#define NSL 100
#define NP  128          // slots padded to 128
#define DD  64
#define BSR (BB*SS)      // 4096 rows

typedef unsigned long long ull;

// -------- scratch (no allocations allowed) --------
__device__ float g_gate[BSR];
__device__ float g_KW[HH*NP];       // (W_q^T keys^T)[h][n], pad n>=100 with 0
__device__ float g_logrelp[NP];     // log(rel+eps), pad = -1e30
__device__ float g_attn[BSR*NP];    // softmax(scores), un-gated
__device__ unsigned g_row_ticket;

// -------- packed f32x2 helpers --------
__device__ __forceinline__ ull pk2(float lo, float hi){
    ull r; asm("mov.b64 %0, {%1, %2};" : "=l"(r) : "f"(lo), "f"(hi)); return r;
}
__device__ __forceinline__ void upk2(ull v, float& lo, float& hi){
    asm("mov.b64 {%0, %1}, %2;" : "=f"(lo), "=f"(hi) : "l"(v));
}
__device__ __forceinline__ void fma2(ull& d, ull a, ull b){
    asm("fma.rn.f32x2 %0, %1, %2, %0;" : "+l"(d) : "l"(a), "l"(b));
}
union F4U { float4 f; ull u[2]; };

// ============================================================
// prep_kw: KW[h][n] = sum_d Wq[d][h]*keys[n][d]
// grid (16, 8): block y owns n in [16y, 16y+16) -> 128 CTAs
// ============================================================
__global__ __launch_bounds__(256)
void prep_kw(const float* __restrict__ Wq,
             const float* __restrict__ keys,
             const float* __restrict__ rel)
{
    __shared__ float sk[16*DD];
    int t = threadIdx.x;
    int n0 = blockIdx.y * 16;
    for (int i = t; i < 16*DD; i += 256) {
        int n = i >> 6, d = i & 63;
        sk[i] = ((n0 + n) < NSL) ? keys[(n0+n)*DD + d] : 0.f;
    }
    __syncthreads();

    int h = blockIdx.x*256 + t;
    float wv[DD];
    #pragma unroll
    for (int d = 0; d < DD; ++d) wv[d] = Wq[(size_t)d*HH + h];

    #pragma unroll 4
    for (int n = 0; n < 16; ++n) {
        float acc = 0.f;
        const float* kn = sk + n*DD;
        #pragma unroll
        for (int d = 0; d < DD; ++d) acc += wv[d]*kn[d];
        g_KW[(size_t)h*NP + n0 + n] = acc;
    }
    if (blockIdx.x == 0 && blockIdx.y == 0 && t < NP)
        g_logrelp[t] = (t < NSL) ? __logf(rel[t] + 1e-10f) : -1e30f;
    if (blockIdx.x == 0 && blockIdx.y == 0 && t == 0) g_row_ticket = 0u;
}

// ============================================================
// mega: grid = 296 (2 CTAs/SM).  (exact R6 structure)
//   blocks [0,148)    : entropy ticket loop from t=0
//   blocks [148,276)  : one scores tile, then join entropy
//   blocks [276,296)  : entropy
// ============================================================
#define NENT  148
#define NSCORE 128
#define NGRID (NENT + NSCORE + 20)   // 296

#define SKC 64
#define NCH (HH/SKC)     // 64 chunks
#define SCORES_SMEM (32*SKC*2 + SKC*NP)   // floats: 12288 -> 49152B

__device__ __forceinline__ void entropy_loop(const float* __restrict__ paw,
                                             float w1, float bb,
                                             unsigned* s_work, float* red)
{
    int t = threadIdx.x;
    for (;;) {
        __syncthreads();
        if (t == 0) *s_work = atomicAdd(&g_row_ticket, 1u);
        __syncthreads();
        unsigned row = *s_work;
        if (row >= BSR) break;

        size_t b = (size_t)(row >> 11);
        size_t s = (size_t)(row & 2047);
        const float* base = paw + ((b*NHD)*SS + s) * (size_t)SS;

        float4 a0 = make_float4(0.f,0.f,0.f,0.f);
        float4 a1 = make_float4(0.f,0.f,0.f,0.f);
        for (int h0 = 0; h0 < NHD; h0 += 8) {
            float4 x0[8], x1[8];
            #pragma unroll
            for (int u = 0; u < 8; ++u) {
                const float4* p = (const float4*)(base + (size_t)(h0+u)*SS*SS);
                x0[u] = p[t];
                x1[u] = p[t + 256];
            }
            #pragma unroll
            for (int u = 0; u < 8; ++u) {
                a0.x += x0[u].x; a0.y += x0[u].y; a0.z += x0[u].z; a0.w += x0[u].w;
                a1.x += x1[u].x; a1.y += x1[u].y; a1.z += x1[u].z; a1.w += x1[u].w;
            }
        }
        const float inv = 1.0f / 32.0f;
        float v[8] = {a0.x,a0.y,a0.z,a0.w,a1.x,a1.y,a1.z,a1.w};
        float loc = 0.f;
        #pragma unroll
        for (int i = 0; i < 8; ++i) {
            float a = v[i] * inv;
            loc += a * __logf(a + 1e-10f);
        }
        #pragma unroll
        for (int o = 16; o; o >>= 1) loc += __shfl_xor_sync(0xffffffffu, loc, o);
        if ((t & 31) == 0) red[t >> 5] = loc;
        __syncthreads();
        if (t == 0) {
            float tot = 0.f;
            #pragma unroll
            for (int i = 0; i < 8; ++i) tot += red[i];
            float e = -tot;
            float g = 1.0f / (1.0f + __expf(-(w1*e + bb)));
            if (e < 0.5f)       g = 0.f;
            else if (e > 2.0f)  g = fminf(g, 0.8f);
            g_gate[row] = g;
        }
    }
}

__global__ __launch_bounds__(256, 2)
void mega_kernel(const float* __restrict__ hidden,
                 const float* __restrict__ paw,
                 const float* __restrict__ w1p,
                 const float* __restrict__ bp)
{
    extern __shared__ float smraw[];
    __shared__ float red[8];
    __shared__ unsigned s_work;
    int t = threadIdx.x;
    int bid = blockIdx.x;

    if (bid >= NENT && bid < NENT + NSCORE) {
        // =================== one scores tile ===================
        float2* sh = (float2*)smraw;             // [32][SKC] dup pairs, 16KB
        float*  sw = smraw + 32*SKC*2;           // [SKC][NP], 32KB
        int w = t>>5, lane = t&31;
        int row0 = (bid - NENT)*32;

        float4 ph[2], pw[8];
        #pragma unroll
        for (int i = 0; i < 2; ++i) {
            int idx = t + i*256, rr = idx>>4, c4 = idx&15;
            ph[i] = *(const float4*)(hidden + (size_t)(row0+rr)*HH + (c4<<2));
        }
        #pragma unroll
        for (int i = 0; i < 8; ++i) {
            int idx = t + i*256, kk = idx>>5, c4 = idx&31;
            pw[i] = *(const float4*)(g_KW + (size_t)kk*NP + (c4<<2));
        }

        ull a[4][2] = {{0,0},{0,0},{0,0},{0,0}};

        for (int c = 0; c < NCH; ++c) {
            __syncthreads();
            #pragma unroll
            for (int i = 0; i < 2; ++i) {
                int idx = t + i*256, rr = idx>>4, c4 = idx&15;
                float2* d = &sh[rr*SKC + (c4<<2)];
                d[0] = make_float2(ph[i].x, ph[i].x);
                d[1] = make_float2(ph[i].y, ph[i].y);
                d[2] = make_float2(ph[i].z, ph[i].z);
                d[3] = make_float2(ph[i].w, ph[i].w);
            }
            #pragma unroll
            for (int i = 0; i < 8; ++i) {
                int idx = t + i*256, kk = idx>>5, c4 = idx&31;
                *(float4*)(sw + kk*NP + (c4<<2)) = pw[i];
            }
            __syncthreads();

            if (c + 1 < NCH) {
                int k0 = (c+1)*SKC;
                #pragma unroll
                for (int i = 0; i < 2; ++i) {
                    int idx = t + i*256, rr = idx>>4, c4 = idx&15;
                    ph[i] = *(const float4*)(hidden + (size_t)(row0+rr)*HH + k0 + (c4<<2));
                }
                #pragma unroll
                for (int i = 0; i < 8; ++i) {
                    int idx = t + i*256, kk = idx>>5, c4 = idx&31;
                    pw[i] = *(const float4*)(g_KW + (size_t)(k0+kk)*NP + (c4<<2));
                }
            }

            const ull* h0 = (const ull*)&sh[(w*4+0)*SKC];
            const ull* h1 = (const ull*)&sh[(w*4+1)*SKC];
            const ull* h2 = (const ull*)&sh[(w*4+2)*SKC];
            const ull* h3 = (const ull*)&sh[(w*4+3)*SKC];
            #pragma unroll 8
            for (int k = 0; k < SKC; ++k) {
                F4U kw; kw.f = *(const float4*)(sw + k*NP + (lane<<2));
                ull hh0 = h0[k], hh1 = h1[k], hh2 = h2[k], hh3 = h3[k];
                fma2(a[0][0], kw.u[0], hh0); fma2(a[0][1], kw.u[1], hh0);
                fma2(a[1][0], kw.u[0], hh1); fma2(a[1][1], kw.u[1], hh1);
                fma2(a[2][0], kw.u[0], hh2); fma2(a[2][1], kw.u[1], hh2);
                fma2(a[3][0], kw.u[0], hh3); fma2(a[3][1], kw.u[1], hh3);
            }
        }

        // softmax per row (pad n>=100 has logrel=-1e30 -> exp=0)
        float4 lr = *(const float4*)(g_logrelp + (lane<<2));
        #pragma unroll
        for (int j = 0; j < 4; ++j) {
            int row = row0 + w*4 + j;
            float s0,s1,s2,s3;
            upk2(a[j][0], s0, s1); upk2(a[j][1], s2, s3);
            s0 = 0.125f*s0 + lr.x; s1 = 0.125f*s1 + lr.y;
            s2 = 0.125f*s2 + lr.z; s3 = 0.125f*s3 + lr.w;
            float m = fmaxf(fmaxf(s0,s1), fmaxf(s2,s3));
            #pragma unroll
            for (int o = 16; o; o >>= 1) m = fmaxf(m, __shfl_xor_sync(0xffffffffu, m, o));
            float e0 = __expf(s0-m), e1 = __expf(s1-m);
            float e2 = __expf(s2-m), e3 = __expf(s3-m);
            float sum = e0+e1+e2+e3;
            #pragma unroll
            for (int o = 16; o; o >>= 1) sum += __shfl_xor_sync(0xffffffffu, sum, o);
            float invs = 1.0f / sum;
            float4 o4 = make_float4(e0*invs, e1*invs, e2*invs, e3*invs);
            *(float4*)(g_attn + (size_t)row*NP + (lane<<2)) = o4;
        }
    }

    // =================== entropy (all CTAs) ===================
    entropy_loop(paw, w1p[0], bp[0], &s_work, red);
}

// ============================================================
// output: out = primary + gate[row]*(attn @ vals)
// grid (128 row-tiles, 8 col-tiles) x 512 thr.
// Each thread: 2 cols x 8 row-pairs (half = t>>8 picks rp 0-7 or 8-15)
// -> per n: 4 LDS.128 feed 16 fma2 (1:4), acc = 16 ull = 32 regs
// -> ~60 regs, 2 CTAs/SM, 32 warps/SM.
// ============================================================
__global__ __launch_bounds__(512, 2)
void output_kernel(const float* __restrict__ primary,
                   const float* __restrict__ vals,
                   float* __restrict__ out)
{
    __shared__ ull attn2[NSL*16];   // [n][row-pair], 12.8KB
    __shared__ float sg[32];
    int t = threadIdx.x;
    int half = t >> 8;              // 0: rp 0-7, 1: rp 8-15
    int tt = t & 255;
    int row0 = blockIdx.x*32;
    int cA = blockIdx.y*512 + tt, cB = cA + 256;
    int rpb = half*8;

    if (t < 32) sg[t] = g_gate[row0 + t];
    __syncthreads();
    for (int idx = t; idx < NSL*16; idx += 512) {
        int n = idx >> 4, rp = idx & 15;
        float a0 = g_attn[(size_t)(row0 + 2*rp  )*NP + n];
        float a1 = g_attn[(size_t)(row0 + 2*rp+1)*NP + n];
        attn2[n*16 + rp] = pk2(a0*sg[2*rp], a1*sg[2*rp+1]);
    }
    __syncthreads();

    ull aA[8], aB[8];
    #pragma unroll
    for (int rp = 0; rp < 8; ++rp) {
        size_t rb = (size_t)(row0 + (rpb + rp)*2) * HH;
        aA[rp] = pk2(primary[rb + cA], primary[rb + HH + cA]);
        aB[rp] = pk2(primary[rb + cB], primary[rb + HH + cB]);
    }

    // 4-deep prefetch ring on vals (L2-resident)
    float vA[4], vB[4];
    #pragma unroll
    for (int i = 0; i < 4; ++i) {
        vA[i] = vals[(size_t)i*HH + cA];
        vB[i] = vals[(size_t)i*HH + cB];
    }

    for (int n = 0; n < NSL; ++n) {
        int np = (n + 4 < NSL) ? n + 4 : NSL-1;
        float nvA = vals[(size_t)np*HH + cA];
        float nvB = vals[(size_t)np*HH + cB];
        int sl = n & 3;
        ull vvA = pk2(vA[sl], vA[sl]), vvB = pk2(vB[sl], vB[sl]);
        const float4* arow = (const float4*)(attn2 + n*16 + rpb);
        #pragma unroll
        for (int j = 0; j < 4; ++j) {
            F4U u; u.f = arow[j];        // broadcast LDS.128 -> 4 fma2
            fma2(aA[2*j],   u.u[0], vvA);
            fma2(aA[2*j+1], u.u[1], vvA);
            fma2(aB[2*j],   u.u[0], vvB);
            fma2(aB[2*j+1], u.u[1], vvB);
        }
        vA[sl] = nvA; vB[sl] = nvB;
    }

    #pragma unroll
    for (int rp = 0; rp < 8; ++rp) {
        float x, y;
        size_t rb = (size_t)(row0 + (rpb + rp)*2) * HH;
        upk2(aA[rp], x, y); out[rb + cA] = x; out[rb + HH + cA] = y;
        upk2(aB[rp], x, y); out[rb + cB] = x; out[rb + HH + cB] = y;
    }
}

// ============================================================
extern "C" void kernel_launch(void* const* d_in, const int* in_sizes, int n_in,
                              void* d_out, int out_size)
{
    const float* hidden  = (const float*)d_in[0];  // [B,S,H]
    const float* primary = (const float*)d_in[1];  // [B,S,H]
    const float* paw     = (const float*)d_in[2];  // [B,NH,S,S]
    const float* rel     = (const float*)d_in[3];  // [NS]
    const float* Wq      = (const float*)d_in[4];  // [D,H]
    const float* keys    = (const float*)d_in[5];  // [NS,D]
    const float* vals    = (const float*)d_in[6];  // [NS,H]
    const float* gw1     = (const float*)d_in[7];  // scalar
    const float* gb      = (const float*)d_in[8];  // scalar
    float* out = (float*)d_out;

    cudaFuncSetAttribute(mega_kernel,
                         cudaFuncAttributeMaxDynamicSharedMemorySize,
                         SCORES_SMEM * (int)sizeof(float));

    prep_kw<<<dim3(HH/256, 8), 256>>>(Wq, keys, rel);
    mega_kernel<<<NGRID, 256, SCORES_SMEM * sizeof(float)>>>(hidden, paw, gw1, gb);
    output_kernel<<<dim3(BSR/32, 8), 512>>>(primary, vals, out);
}

// round 11
// speedup vs baseline: 2.0801x; 1.2203x over previous
#include <cuda_runtime.h>

// Problem shapes (fixed per reference setup_inputs)
#define BB  2
#define SS  2048
#define HH  4096
#define NHD 32
#define NSL 100
#define NP  128          // slots padded to 128
#define DD  64
#define BSR (BB*SS)      // 4096 rows

typedef unsigned long long ull;

// -------- scratch (no allocations allowed) --------
__device__ float g_gate[BSR];
__device__ float g_KW[HH*NP];       // (W_q^T keys^T)[h][n], pad n>=100 with 0
__device__ float g_logrelp[NP];     // log(rel+eps), pad = -1e30
__device__ float g_attn[BSR*NP];    // softmax(scores), un-gated
__device__ unsigned g_row_ticket;

// -------- packed f32x2 helpers --------
__device__ __forceinline__ ull pk2(float lo, float hi){
    ull r; asm("mov.b64 %0, {%1, %2};" : "=l"(r) : "f"(lo), "f"(hi)); return r;
}
__device__ __forceinline__ void upk2(ull v, float& lo, float& hi){
    asm("mov.b64 {%0, %1}, %2;" : "=f"(lo), "=f"(hi) : "l"(v));
}
__device__ __forceinline__ void fma2(ull& d, ull a, ull b){
    asm("fma.rn.f32x2 %0, %1, %2, %0;" : "+l"(d) : "l"(a), "l"(b));
}
union F4U { float4 f; ull u[2]; };

// ============================================================
// prep_kw: KW[h][n] = sum_d Wq[d][h]*keys[n][d]
// grid (16, 8): block y owns n in [16y, 16y+16) -> 128 CTAs
// (R7 version, measured 10.7us)
// ============================================================
__global__ __launch_bounds__(256)
void prep_kw(const float* __restrict__ Wq,
             const float* __restrict__ keys,
             const float* __restrict__ rel)
{
    __shared__ float sk[16*DD];
    int t = threadIdx.x;
    int n0 = blockIdx.y * 16;
    for (int i = t; i < 16*DD; i += 256) {
        int n = i >> 6, d = i & 63;
        sk[i] = ((n0 + n) < NSL) ? keys[(n0+n)*DD + d] : 0.f;
    }
    __syncthreads();

    int h = blockIdx.x*256 + t;
    float wv[DD];
    #pragma unroll
    for (int d = 0; d < DD; ++d) wv[d] = Wq[(size_t)d*HH + h];

    #pragma unroll 4
    for (int n = 0; n < 16; ++n) {
        float acc = 0.f;
        const float* kn = sk + n*DD;
        #pragma unroll
        for (int d = 0; d < DD; ++d) acc += wv[d]*kn[d];
        g_KW[(size_t)h*NP + n0 + n] = acc;
    }
    if (blockIdx.x == 0 && blockIdx.y == 0 && t < NP)
        g_logrelp[t] = (t < NSL) ? __logf(rel[t] + 1e-10f) : -1e30f;
    if (blockIdx.x == 0 && blockIdx.y == 0 && t == 0) g_row_ticket = 0u;
}

// ============================================================
// mega: grid = 296 (2 CTAs/SM).  (exact R6 structure)
//   blocks [0,148)    : entropy ticket loop from t=0
//   blocks [148,276)  : one scores tile, then join entropy
//   blocks [276,296)  : entropy
// ============================================================
#define NENT  148
#define NSCORE 128
#define NGRID (NENT + NSCORE + 20)   // 296

#define SKC 64
#define NCH (HH/SKC)     // 64 chunks
#define SCORES_SMEM (32*SKC*2 + SKC*NP)   // floats: 12288 -> 49152B

__device__ __forceinline__ void entropy_loop(const float* __restrict__ paw,
                                             float w1, float bb,
                                             unsigned* s_work, float* red)
{
    int t = threadIdx.x;
    for (;;) {
        __syncthreads();
        if (t == 0) *s_work = atomicAdd(&g_row_ticket, 1u);
        __syncthreads();
        unsigned row = *s_work;
        if (row >= BSR) break;

        size_t b = (size_t)(row >> 11);
        size_t s = (size_t)(row & 2047);
        const float* base = paw + ((b*NHD)*SS + s) * (size_t)SS;

        float4 a0 = make_float4(0.f,0.f,0.f,0.f);
        float4 a1 = make_float4(0.f,0.f,0.f,0.f);
        for (int h0 = 0; h0 < NHD; h0 += 8) {
            float4 x0[8], x1[8];
            #pragma unroll
            for (int u = 0; u < 8; ++u) {
                const float4* p = (const float4*)(base + (size_t)(h0+u)*SS*SS);
                x0[u] = p[t];
                x1[u] = p[t + 256];
            }
            #pragma unroll
            for (int u = 0; u < 8; ++u) {
                a0.x += x0[u].x; a0.y += x0[u].y; a0.z += x0[u].z; a0.w += x0[u].w;
                a1.x += x1[u].x; a1.y += x1[u].y; a1.z += x1[u].z; a1.w += x1[u].w;
            }
        }
        const float inv = 1.0f / 32.0f;
        float v[8] = {a0.x,a0.y,a0.z,a0.w,a1.x,a1.y,a1.z,a1.w};
        float loc = 0.f;
        #pragma unroll
        for (int i = 0; i < 8; ++i) {
            float a = v[i] * inv;
            loc += a * __logf(a + 1e-10f);
        }
        #pragma unroll
        for (int o = 16; o; o >>= 1) loc += __shfl_xor_sync(0xffffffffu, loc, o);
        if ((t & 31) == 0) red[t >> 5] = loc;
        __syncthreads();
        if (t == 0) {
            float tot = 0.f;
            #pragma unroll
            for (int i = 0; i < 8; ++i) tot += red[i];
            float e = -tot;
            float g = 1.0f / (1.0f + __expf(-(w1*e + bb)));
            if (e < 0.5f)       g = 0.f;
            else if (e > 2.0f)  g = fminf(g, 0.8f);
            g_gate[row] = g;
        }
    }
}

__global__ __launch_bounds__(256, 2)
void mega_kernel(const float* __restrict__ hidden,
                 const float* __restrict__ paw,
                 const float* __restrict__ w1p,
                 const float* __restrict__ bp)
{
    extern __shared__ float smraw[];
    __shared__ float red[8];
    __shared__ unsigned s_work;
    int t = threadIdx.x;
    int bid = blockIdx.x;

    if (bid >= NENT && bid < NENT + NSCORE) {
        // =================== one scores tile ===================
        float2* sh = (float2*)smraw;             // [32][SKC] dup pairs, 16KB
        float*  sw = smraw + 32*SKC*2;           // [SKC][NP], 32KB
        int w = t>>5, lane = t&31;
        int row0 = (bid - NENT)*32;

        float4 ph[2], pw[8];
        #pragma unroll
        for (int i = 0; i < 2; ++i) {
            int idx = t + i*256, rr = idx>>4, c4 = idx&15;
            ph[i] = *(const float4*)(hidden + (size_t)(row0+rr)*HH + (c4<<2));
        }
        #pragma unroll
        for (int i = 0; i < 8; ++i) {
            int idx = t + i*256, kk = idx>>5, c4 = idx&31;
            pw[i] = *(const float4*)(g_KW + (size_t)kk*NP + (c4<<2));
        }

        ull a[4][2] = {{0,0},{0,0},{0,0},{0,0}};

        for (int c = 0; c < NCH; ++c) {
            __syncthreads();
            #pragma unroll
            for (int i = 0; i < 2; ++i) {
                int idx = t + i*256, rr = idx>>4, c4 = idx&15;
                float2* d = &sh[rr*SKC + (c4<<2)];
                d[0] = make_float2(ph[i].x, ph[i].x);
                d[1] = make_float2(ph[i].y, ph[i].y);
                d[2] = make_float2(ph[i].z, ph[i].z);
                d[3] = make_float2(ph[i].w, ph[i].w);
            }
            #pragma unroll
            for (int i = 0; i < 8; ++i) {
                int idx = t + i*256, kk = idx>>5, c4 = idx&31;
                *(float4*)(sw + kk*NP + (c4<<2)) = pw[i];
            }
            __syncthreads();

            if (c + 1 < NCH) {
                int k0 = (c+1)*SKC;
                #pragma unroll
                for (int i = 0; i < 2; ++i) {
                    int idx = t + i*256, rr = idx>>4, c4 = idx&15;
                    ph[i] = *(const float4*)(hidden + (size_t)(row0+rr)*HH + k0 + (c4<<2));
                }
                #pragma unroll
                for (int i = 0; i < 8; ++i) {
                    int idx = t + i*256, kk = idx>>5, c4 = idx&31;
                    pw[i] = *(const float4*)(g_KW + (size_t)(k0+kk)*NP + (c4<<2));
                }
            }

            const ull* h0 = (const ull*)&sh[(w*4+0)*SKC];
            const ull* h1 = (const ull*)&sh[(w*4+1)*SKC];
            const ull* h2 = (const ull*)&sh[(w*4+2)*SKC];
            const ull* h3 = (const ull*)&sh[(w*4+3)*SKC];
            #pragma unroll 8
            for (int k = 0; k < SKC; ++k) {
                F4U kw; kw.f = *(const float4*)(sw + k*NP + (lane<<2));
                ull hh0 = h0[k], hh1 = h1[k], hh2 = h2[k], hh3 = h3[k];
                fma2(a[0][0], kw.u[0], hh0); fma2(a[0][1], kw.u[1], hh0);
                fma2(a[1][0], kw.u[0], hh1); fma2(a[1][1], kw.u[1], hh1);
                fma2(a[2][0], kw.u[0], hh2); fma2(a[2][1], kw.u[1], hh2);
                fma2(a[3][0], kw.u[0], hh3); fma2(a[3][1], kw.u[1], hh3);
            }
        }

        // softmax per row (pad n>=100 has logrel=-1e30 -> exp=0)
        float4 lr = *(const float4*)(g_logrelp + (lane<<2));
        #pragma unroll
        for (int j = 0; j < 4; ++j) {
            int row = row0 + w*4 + j;
            float s0,s1,s2,s3;
            upk2(a[j][0], s0, s1); upk2(a[j][1], s2, s3);
            s0 = 0.125f*s0 + lr.x; s1 = 0.125f*s1 + lr.y;
            s2 = 0.125f*s2 + lr.z; s3 = 0.125f*s3 + lr.w;
            float m = fmaxf(fmaxf(s0,s1), fmaxf(s2,s3));
            #pragma unroll
            for (int o = 16; o; o >>= 1) m = fmaxf(m, __shfl_xor_sync(0xffffffffu, m, o));
            float e0 = __expf(s0-m), e1 = __expf(s1-m);
            float e2 = __expf(s2-m), e3 = __expf(s3-m);
            float sum = e0+e1+e2+e3;
            #pragma unroll
            for (int o = 16; o; o >>= 1) sum += __shfl_xor_sync(0xffffffffu, sum, o);
            float invs = 1.0f / sum;
            float4 o4 = make_float4(e0*invs, e1*invs, e2*invs, e3*invs);
            *(float4*)(g_attn + (size_t)row*NP + (lane<<2)) = o4;
        }
    }

    // =================== entropy (all CTAs) ===================
    entropy_loop(paw, w1p[0], bp[0], &s_work, red);
}

// ============================================================
// output: out = primary + gate[row]*(attn @ vals)
// grid (128 row-tiles, 8 col-tiles) x 512 thr; 1 col/thread,
// 16 packed row-pair accumulators; 2 CTAs/SM. (exact R6 config)
// ============================================================
__global__ __launch_bounds__(512, 2)
void output_kernel(const float* __restrict__ primary,
                   const float* __restrict__ vals,
                   float* __restrict__ out)
{
    __shared__ ull attn2[NSL*16];   // [n][row-pair], 12.8KB
    __shared__ float sg[32];
    int t = threadIdx.x;
    int row0 = blockIdx.x*32;
    int c = blockIdx.y*512 + t;

    if (t < 32) sg[t] = g_gate[row0 + t];
    __syncthreads();
    for (int idx = t; idx < NSL*16; idx += 512) {
        int n = idx >> 4, rp = idx & 15;
        float a0 = g_attn[(size_t)(row0 + 2*rp  )*NP + n];
        float a1 = g_attn[(size_t)(row0 + 2*rp+1)*NP + n];
        attn2[n*16 + rp] = pk2(a0*sg[2*rp], a1*sg[2*rp+1]);
    }
    __syncthreads();

    ull acc[16];
    #pragma unroll
    for (int rp = 0; rp < 16; ++rp) {
        size_t rb = (size_t)(row0 + rp*2) * HH;
        acc[rp] = pk2(primary[rb + c], primary[rb + HH + c]);
    }

    // 4-deep prefetch ring on vals (L2-resident)
    float vr[4];
    #pragma unroll
    for (int i = 0; i < 4; ++i) vr[i] = vals[(size_t)i*HH + c];

    for (int n = 0; n < NSL; ++n) {
        int np = (n + 4 < NSL) ? n + 4 : NSL-1;
        float nv = vals[(size_t)np*HH + c];
        int sl = n & 3;
        ull vv = pk2(vr[sl], vr[sl]);
        const float4* arow = (const float4*)(attn2 + n*16);
        #pragma unroll
        for (int j = 0; j < 8; ++j) {
            F4U u; u.f = arow[j];        // broadcast LDS.128
            fma2(acc[2*j],   u.u[0], vv);
            fma2(acc[2*j+1], u.u[1], vv);
        }
        vr[sl] = nv;
    }

    #pragma unroll
    for (int rp = 0; rp < 16; ++rp) {
        float x, y;
        size_t rb = (size_t)(row0 + rp*2) * HH;
        upk2(acc[rp], x, y);
        out[rb + c] = x;
        out[rb + HH + c] = y;
    }
}

// ============================================================
extern "C" void kernel_launch(void* const* d_in, const int* in_sizes, int n_in,
                              void* d_out, int out_size)
{
    const float* hidden  = (const float*)d_in[0];  // [B,S,H]
    const float* primary = (const float*)d_in[1];  // [B,S,H]
    const float* paw     = (const float*)d_in[2];  // [B,NH,S,S]
    const float* rel     = (const float*)d_in[3];  // [NS]
    const float* Wq      = (const float*)d_in[4];  // [D,H]
    const float* keys    = (const float*)d_in[5];  // [NS,D]
    const float* vals    = (const float*)d_in[6];  // [NS,H]
    const float* gw1     = (const float*)d_in[7];  // scalar
    const float* gb      = (const float*)d_in[8];  // scalar
    float* out = (float*)d_out;

    cudaFuncSetAttribute(mega_kernel,
                         cudaFuncAttributeMaxDynamicSharedMemorySize,
                         SCORES_SMEM * (int)sizeof(float));

    prep_kw<<<dim3(HH/256, 8), 256>>>(Wq, keys, rel);
    mega_kernel<<<NGRID, 256, SCORES_SMEM * sizeof(float)>>>(hidden, paw, gw1, gb);
    output_kernel<<<dim3(BSR/32, 8), 512>>>(primary, vals, out);
}

// round 12
// speedup vs baseline: 2.1567x; 1.0368x over previous
#include <cuda_runtime.h>

// Problem shapes (fixed per reference setup_inputs)
#define BB  2
#define SS  2048
#define HH  4096
#define NHD 32
#define NSL 100
#define NP  128          // slots padded to 128
#define DD  64
#define BSR (BB*SS)      // 4096 rows

typedef unsigned long long ull;

// -------- scratch (no allocations allowed) --------
__device__ float g_gate[BSR];
__device__ float g_KW[HH*NP];       // (W_q^T keys^T)[h][n], pad n>=100 with 0
__device__ float g_logrelp[NP];     // log(rel+eps), pad = -1e30
__device__ float g_attn[BSR*NP];    // softmax(scores), un-gated
__device__ unsigned g_row_ticket;
__device__ unsigned g_out_ticket;

// -------- packed f32x2 helpers --------
__device__ __forceinline__ ull pk2(float lo, float hi){
    ull r; asm("mov.b64 %0, {%1, %2};" : "=l"(r) : "f"(lo), "f"(hi)); return r;
}
__device__ __forceinline__ void upk2(ull v, float& lo, float& hi){
    asm("mov.b64 {%0, %1}, %2;" : "=f"(lo), "=f"(hi) : "l"(v));
}
__device__ __forceinline__ void fma2(ull& d, ull a, ull b){
    asm("fma.rn.f32x2 %0, %1, %2, %0;" : "+l"(d) : "l"(a), "l"(b));
}
union F4U { float4 f; ull u[2]; };

// ============================================================
// reset: tickets only (also shifts the ncu -s window)
// ============================================================
__global__ void reset_kernel()
{
    if (threadIdx.x == 0) { g_row_ticket = 0u; g_out_ticket = 0u; }
}

// ============================================================
// prep_kw: KW[h][n] = sum_d Wq[d][h]*keys[n][d]
// grid (16, 8): block y owns n in [16y, 16y+16) -> 128 CTAs
// ============================================================
__global__ __launch_bounds__(256)
void prep_kw(const float* __restrict__ Wq,
             const float* __restrict__ keys,
             const float* __restrict__ rel)
{
    __shared__ float sk[16*DD];
    int t = threadIdx.x;
    int n0 = blockIdx.y * 16;
    for (int i = t; i < 16*DD; i += 256) {
        int n = i >> 6, d = i & 63;
        sk[i] = ((n0 + n) < NSL) ? keys[(n0+n)*DD + d] : 0.f;
    }
    __syncthreads();

    int h = blockIdx.x*256 + t;
    float wv[DD];
    #pragma unroll
    for (int d = 0; d < DD; ++d) wv[d] = Wq[(size_t)d*HH + h];

    #pragma unroll 4
    for (int n = 0; n < 16; ++n) {
        float acc = 0.f;
        const float* kn = sk + n*DD;
        #pragma unroll
        for (int d = 0; d < DD; ++d) acc += wv[d]*kn[d];
        g_KW[(size_t)h*NP + n0 + n] = acc;
    }
    if (blockIdx.x == 0 && blockIdx.y == 0 && t < NP)
        g_logrelp[t] = (t < NSL) ? __logf(rel[t] + 1e-10f) : -1e30f;
}

// ============================================================
// mega: grid = 296 (2 CTAs/SM).  (exact R6 structure)
//   blocks [0,148)    : entropy ticket loop from t=0
//   blocks [148,276)  : one scores tile, then join entropy
//   blocks [276,296)  : entropy
// ============================================================
#define NENT  148
#define NSCORE 128
#define NGRID (NENT + NSCORE + 20)   // 296

#define SKC 64
#define NCH (HH/SKC)     // 64 chunks
#define SCORES_SMEM (32*SKC*2 + SKC*NP)   // floats: 12288 -> 49152B

__device__ __forceinline__ void entropy_loop(const float* __restrict__ paw,
                                             float w1, float bb,
                                             unsigned* s_work, float* red)
{
    int t = threadIdx.x;
    for (;;) {
        __syncthreads();
        if (t == 0) *s_work = atomicAdd(&g_row_ticket, 1u);
        __syncthreads();
        unsigned row = *s_work;
        if (row >= BSR) break;

        size_t b = (size_t)(row >> 11);
        size_t s = (size_t)(row & 2047);
        const float* base = paw + ((b*NHD)*SS + s) * (size_t)SS;

        float4 a0 = make_float4(0.f,0.f,0.f,0.f);
        float4 a1 = make_float4(0.f,0.f,0.f,0.f);
        for (int h0 = 0; h0 < NHD; h0 += 8) {
            float4 x0[8], x1[8];
            #pragma unroll
            for (int u = 0; u < 8; ++u) {
                const float4* p = (const float4*)(base + (size_t)(h0+u)*SS*SS);
                x0[u] = p[t];
                x1[u] = p[t + 256];
            }
            #pragma unroll
            for (int u = 0; u < 8; ++u) {
                a0.x += x0[u].x; a0.y += x0[u].y; a0.z += x0[u].z; a0.w += x0[u].w;
                a1.x += x1[u].x; a1.y += x1[u].y; a1.z += x1[u].z; a1.w += x1[u].w;
            }
        }
        const float inv = 1.0f / 32.0f;
        float v[8] = {a0.x,a0.y,a0.z,a0.w,a1.x,a1.y,a1.z,a1.w};
        float loc = 0.f;
        #pragma unroll
        for (int i = 0; i < 8; ++i) {
            float a = v[i] * inv;
            loc += a * __logf(a + 1e-10f);
        }
        #pragma unroll
        for (int o = 16; o; o >>= 1) loc += __shfl_xor_sync(0xffffffffu, loc, o);
        if ((t & 31) == 0) red[t >> 5] = loc;
        __syncthreads();
        if (t == 0) {
            float tot = 0.f;
            #pragma unroll
            for (int i = 0; i < 8; ++i) tot += red[i];
            float e = -tot;
            float g = 1.0f / (1.0f + __expf(-(w1*e + bb)));
            if (e < 0.5f)       g = 0.f;
            else if (e > 2.0f)  g = fminf(g, 0.8f);
            g_gate[row] = g;
        }
    }
}

__global__ __launch_bounds__(256, 2)
void mega_kernel(const float* __restrict__ hidden,
                 const float* __restrict__ paw,
                 const float* __restrict__ w1p,
                 const float* __restrict__ bp)
{
    extern __shared__ float smraw[];
    __shared__ float red[8];
    __shared__ unsigned s_work;
    int t = threadIdx.x;
    int bid = blockIdx.x;

    if (bid >= NENT && bid < NENT + NSCORE) {
        // =================== one scores tile ===================
        float2* sh = (float2*)smraw;             // [32][SKC] dup pairs, 16KB
        float*  sw = smraw + 32*SKC*2;           // [SKC][NP], 32KB
        int w = t>>5, lane = t&31;
        int row0 = (bid - NENT)*32;

        float4 ph[2], pw[8];
        #pragma unroll
        for (int i = 0; i < 2; ++i) {
            int idx = t + i*256, rr = idx>>4, c4 = idx&15;
            ph[i] = *(const float4*)(hidden + (size_t)(row0+rr)*HH + (c4<<2));
        }
        #pragma unroll
        for (int i = 0; i < 8; ++i) {
            int idx = t + i*256, kk = idx>>5, c4 = idx&31;
            pw[i] = *(const float4*)(g_KW + (size_t)kk*NP + (c4<<2));
        }

        ull a[4][2] = {{0,0},{0,0},{0,0},{0,0}};

        for (int c = 0; c < NCH; ++c) {
            __syncthreads();
            #pragma unroll
            for (int i = 0; i < 2; ++i) {
                int idx = t + i*256, rr = idx>>4, c4 = idx&15;
                float2* d = &sh[rr*SKC + (c4<<2)];
                d[0] = make_float2(ph[i].x, ph[i].x);
                d[1] = make_float2(ph[i].y, ph[i].y);
                d[2] = make_float2(ph[i].z, ph[i].z);
                d[3] = make_float2(ph[i].w, ph[i].w);
            }
            #pragma unroll
            for (int i = 0; i < 8; ++i) {
                int idx = t + i*256, kk = idx>>5, c4 = idx&31;
                *(float4*)(sw + kk*NP + (c4<<2)) = pw[i];
            }
            __syncthreads();

            if (c + 1 < NCH) {
                int k0 = (c+1)*SKC;
                #pragma unroll
                for (int i = 0; i < 2; ++i) {
                    int idx = t + i*256, rr = idx>>4, c4 = idx&15;
                    ph[i] = *(const float4*)(hidden + (size_t)(row0+rr)*HH + k0 + (c4<<2));
                }
                #pragma unroll
                for (int i = 0; i < 8; ++i) {
                    int idx = t + i*256, kk = idx>>5, c4 = idx&31;
                    pw[i] = *(const float4*)(g_KW + (size_t)(k0+kk)*NP + (c4<<2));
                }
            }

            const ull* h0 = (const ull*)&sh[(w*4+0)*SKC];
            const ull* h1 = (const ull*)&sh[(w*4+1)*SKC];
            const ull* h2 = (const ull*)&sh[(w*4+2)*SKC];
            const ull* h3 = (const ull*)&sh[(w*4+3)*SKC];
            #pragma unroll 8
            for (int k = 0; k < SKC; ++k) {
                F4U kw; kw.f = *(const float4*)(sw + k*NP + (lane<<2));
                ull hh0 = h0[k], hh1 = h1[k], hh2 = h2[k], hh3 = h3[k];
                fma2(a[0][0], kw.u[0], hh0); fma2(a[0][1], kw.u[1], hh0);
                fma2(a[1][0], kw.u[0], hh1); fma2(a[1][1], kw.u[1], hh1);
                fma2(a[2][0], kw.u[0], hh2); fma2(a[2][1], kw.u[1], hh2);
                fma2(a[3][0], kw.u[0], hh3); fma2(a[3][1], kw.u[1], hh3);
            }
        }

        // softmax per row (pad n>=100 has logrel=-1e30 -> exp=0)
        float4 lr = *(const float4*)(g_logrelp + (lane<<2));
        #pragma unroll
        for (int j = 0; j < 4; ++j) {
            int row = row0 + w*4 + j;
            float s0,s1,s2,s3;
            upk2(a[j][0], s0, s1); upk2(a[j][1], s2, s3);
            s0 = 0.125f*s0 + lr.x; s1 = 0.125f*s1 + lr.y;
            s2 = 0.125f*s2 + lr.z; s3 = 0.125f*s3 + lr.w;
            float m = fmaxf(fmaxf(s0,s1), fmaxf(s2,s3));
            #pragma unroll
            for (int o = 16; o; o >>= 1) m = fmaxf(m, __shfl_xor_sync(0xffffffffu, m, o));
            float e0 = __expf(s0-m), e1 = __expf(s1-m);
            float e2 = __expf(s2-m), e3 = __expf(s3-m);
            float sum = e0+e1+e2+e3;
            #pragma unroll
            for (int o = 16; o; o >>= 1) sum += __shfl_xor_sync(0xffffffffu, sum, o);
            float invs = 1.0f / sum;
            float4 o4 = make_float4(e0*invs, e1*invs, e2*invs, e3*invs);
            *(float4*)(g_attn + (size_t)row*NP + (lane<<2)) = o4;
        }
    }

    // =================== entropy (all CTAs) ===================
    entropy_loop(paw, w1p[0], bp[0], &s_work, red);
}

// ============================================================
// output: out = primary + gate[row]*(attn @ vals)
// PERSISTENT: grid 296 x 512 thr, ticket loop over 1024 tiles
// (tile = 32 rows x 512 cols). Inner structure identical to the
// proven R6 config: 1 col/thread, acc[16], 4-deep vals ring.
// ============================================================
#define NOTILE (BSR/32 * 8)   // 1024 tiles

__global__ __launch_bounds__(512, 2)
void output_kernel(const float* __restrict__ primary,
                   const float* __restrict__ vals,
                   float* __restrict__ out)
{
    __shared__ ull attn2[NSL*16];   // [n][row-pair], 12.8KB
    __shared__ float sg[32];
    __shared__ unsigned s_tile;
    int t = threadIdx.x;

    for (;;) {
        __syncthreads();             // previous tile's attn2 reads done
        if (t == 0) s_tile = atomicAdd(&g_out_ticket, 1u);
        __syncthreads();
        unsigned tile = s_tile;
        if (tile >= NOTILE) break;

        int row0 = (int)(tile >> 3) * 32;
        int c    = (int)(tile & 7) * 512 + t;

        if (t < 32) sg[t] = g_gate[row0 + t];
        __syncthreads();
        for (int idx = t; idx < NSL*16; idx += 512) {
            int n = idx >> 4, rp = idx & 15;
            float a0 = g_attn[(size_t)(row0 + 2*rp  )*NP + n];
            float a1 = g_attn[(size_t)(row0 + 2*rp+1)*NP + n];
            attn2[n*16 + rp] = pk2(a0*sg[2*rp], a1*sg[2*rp+1]);
        }
        __syncthreads();

        ull acc[16];
        #pragma unroll
        for (int rp = 0; rp < 16; ++rp) {
            size_t rb = (size_t)(row0 + rp*2) * HH;
            acc[rp] = pk2(primary[rb + c], primary[rb + HH + c]);
        }

        // 4-deep prefetch ring on vals (L2-resident)
        float vr[4];
        #pragma unroll
        for (int i = 0; i < 4; ++i) vr[i] = vals[(size_t)i*HH + c];

        for (int n = 0; n < NSL; ++n) {
            int np = (n + 4 < NSL) ? n + 4 : NSL-1;
            float nv = vals[(size_t)np*HH + c];
            int sl = n & 3;
            ull vv = pk2(vr[sl], vr[sl]);
            const float4* arow = (const float4*)(attn2 + n*16);
            #pragma unroll
            for (int j = 0; j < 8; ++j) {
                F4U u; u.f = arow[j];        // broadcast LDS.128
                fma2(acc[2*j],   u.u[0], vv);
                fma2(acc[2*j+1], u.u[1], vv);
            }
            vr[sl] = nv;
        }

        #pragma unroll
        for (int rp = 0; rp < 16; ++rp) {
            float x, y;
            size_t rb = (size_t)(row0 + rp*2) * HH;
            upk2(acc[rp], x, y);
            out[rb + c] = x;
            out[rb + HH + c] = y;
        }
    }
}

// ============================================================
extern "C" void kernel_launch(void* const* d_in, const int* in_sizes, int n_in,
                              void* d_out, int out_size)
{
    const float* hidden  = (const float*)d_in[0];  // [B,S,H]
    const float* primary = (const float*)d_in[1];  // [B,S,H]
    const float* paw     = (const float*)d_in[2];  // [B,NH,S,S]
    const float* rel     = (const float*)d_in[3];  // [NS]
    const float* Wq      = (const float*)d_in[4];  // [D,H]
    const float* keys    = (const float*)d_in[5];  // [NS,D]
    const float* vals    = (const float*)d_in[6];  // [NS,H]
    const float* gw1     = (const float*)d_in[7];  // scalar
    const float* gb      = (const float*)d_in[8];  // scalar
    float* out = (float*)d_out;

    cudaFuncSetAttribute(mega_kernel,
                         cudaFuncAttributeMaxDynamicSharedMemorySize,
                         SCORES_SMEM * (int)sizeof(float));

    reset_kernel<<<1, 32>>>();
    prep_kw<<<dim3(HH/256, 8), 256>>>(Wq, keys, rel);
    mega_kernel<<<NGRID, 256, SCORES_SMEM * sizeof(float)>>>(hidden, paw, gw1, gb);
    output_kernel<<<NGRID, 512>>>(primary, vals, out);
}